// round 1
// baseline (speedup 1.0000x reference)
#include <cuda_runtime.h>
#include <math.h>

#define N_GENES 10000
#define N_CELLS 8192
#define ZDIM    100
#define KDIM    32
#define HDIM    256

#define TG 63
#define TC 32
#define NSPLIT 4
#define CELLS_PER_SPLIT (N_CELLS / NSPLIT)   // 2048
#define NTILES (CELLS_PER_SPLIT / TC)        // 64
#define GTILES ((N_GENES + TG - 1) / TG)     // 159

// ---------------- scratch (static device memory; no allocations) ------------
__device__ float d_key[N_CELLS * KDIM];                         // (8192, 32)
__device__ float d_query[N_GENES * KDIM];                       // (10000, 32)
__device__ float d_genZT[N_CELLS * ZDIM];                       // (8192, 100)
__device__ float d_pnum[(size_t)NSPLIT * N_GENES * ZDIM];       // 16 MB partials
__device__ float d_pden[NSPLIT * N_GENES];

// ---------------- f32x2 packed-FMA helpers ----------------------------------
__device__ __forceinline__ unsigned long long pack2(float lo, float hi) {
    unsigned long long r;
    asm("mov.b64 %0, {%1, %2};" : "=l"(r) : "f"(lo), "f"(hi));
    return r;
}
__device__ __forceinline__ void unpack2(unsigned long long v, float& lo, float& hi) {
    asm("mov.b64 {%0, %1}, %2;" : "=f"(lo), "=f"(hi) : "l"(v));
}
__device__ __forceinline__ void fma2(unsigned long long& d, unsigned long long a, unsigned long long b) {
    asm("fma.rn.f32x2 %0, %1, %2, %0;" : "+l"(d) : "l"(a), "l"(b));
}
__device__ __forceinline__ float gelu_f(float x) {
    // exact GELU: x * 0.5 * (1 + erf(x / sqrt(2)))   (approximate=False)
    return 0.5f * x * (1.0f + erff(x * 0.70710678118654752440f));
}

// ---------------- K0: transpose gen_Z (100 x 8192) -> genZT (8192 x 100) ----
__global__ void k_transpose(const float* __restrict__ genZ) {
    __shared__ float tile[32][33];
    int c0 = blockIdx.x * 32, z0 = blockIdx.y * 32;
    int tx = threadIdx.x, ty = threadIdx.y;  // (32, 8)
#pragma unroll
    for (int r = 0; r < 32; r += 8) {
        int z = z0 + ty + r;
        tile[ty + r][tx] = (z < ZDIM) ? genZ[(size_t)z * N_CELLS + c0 + tx] : 0.0f;
    }
    __syncthreads();
#pragma unroll
    for (int r = 0; r < 32; r += 8) {
        int c = c0 + ty + r;
        int z = z0 + tx;
        if (z < ZDIM) d_genZT[(size_t)c * ZDIM + z] = tile[tx][ty + r];
    }
}

// ---------------- K1: key MLP: (8192 cells) -> d_key[c][k] ------------------
// block = 256 threads, 32 cells per block, 256 blocks.
__global__ void __launch_bounds__(256) k_key(
    const float* __restrict__ rawZ,
    const float* __restrict__ Wz1, const float* __restrict__ bz1,
    const float* __restrict__ Wz2, const float* __restrict__ bz2)
{
    __shared__ float Zs[ZDIM * 32];    // [z][c]
    __shared__ float hs[HDIM * 33];    // [h][c], stride 33
    const int t  = threadIdx.x;
    const int c0 = blockIdx.x * 32;

    for (int i = t; i < ZDIM * 32; i += 256) {
        int z = i >> 5, c = i & 31;
        Zs[i] = rawZ[(size_t)z * N_CELLS + c0 + c];
    }
    __syncthreads();

    // hidden: this thread owns h = t, all 32 cells
    float acc[32];
    {
        float b = bz1[t];
#pragma unroll
        for (int c = 0; c < 32; c++) acc[c] = b;
    }
    for (int z = 0; z < ZDIM; z++) {
        float w = Wz1[z * HDIM + t];
        const float4* zr = reinterpret_cast<const float4*>(&Zs[z * 32]);
#pragma unroll
        for (int u = 0; u < 8; u++) {
            float4 v = zr[u];
            acc[4*u+0] = fmaf(w, v.x, acc[4*u+0]);
            acc[4*u+1] = fmaf(w, v.y, acc[4*u+1]);
            acc[4*u+2] = fmaf(w, v.z, acc[4*u+2]);
            acc[4*u+3] = fmaf(w, v.w, acc[4*u+3]);
        }
    }
#pragma unroll
    for (int c = 0; c < 32; c++) hs[t * 33 + c] = gelu_f(acc[c]);
    __syncthreads();

    // key: k = t&31, 4 cells per thread
    const int k = t & 31, cg = t >> 5;
    float a0 = bz2[k], a1 = a0, a2 = a0, a3 = a0;
    for (int h = 0; h < HDIM; h++) {
        float w = Wz2[h * KDIM + k];
        const float* hr = &hs[h * 33 + cg * 4];
        a0 = fmaf(w, hr[0], a0);
        a1 = fmaf(w, hr[1], a1);
        a2 = fmaf(w, hr[2], a2);
        a3 = fmaf(w, hr[3], a3);
    }
    int c = c0 + cg * 4;
    d_key[(size_t)(c + 0) * KDIM + k] = a0;
    d_key[(size_t)(c + 1) * KDIM + k] = a1;
    d_key[(size_t)(c + 2) * KDIM + k] = a2;
    d_key[(size_t)(c + 3) * KDIM + k] = a3;
}

// ---------------- K2: query MLP: (10000 genes) -> d_query[g][k] -------------
// one warp per gene
__global__ void k_query(
    const float* __restrict__ Grep,
    const float* __restrict__ Wg1, const float* __restrict__ bg1,
    const float* __restrict__ Wg2, const float* __restrict__ bg2)
{
    int gene = blockIdx.x * 8 + (threadIdx.x >> 5);
    int k    = threadIdx.x & 31;
    if (gene >= N_GENES) return;
    float h = bg1[k];
    const float* grow = &Grep[(size_t)gene * 100];
    for (int j = 0; j < 100; j++)
        h = fmaf(grow[j], Wg1[j * 32 + k], h);
    h = gelu_f(h);
    float q = bg2[k];
#pragma unroll
    for (int j = 0; j < 32; j++) {
        float hj = __shfl_sync(0xffffffffu, h, j);
        q = fmaf(hj, Wg2[j * 32 + k], q);
    }
    d_query[(size_t)gene * KDIM + k] = q;
}

// ---------------- K3: fused scores+gumbel -> exp -> weighted accumulate -----
// grid = (GTILES, NSPLIT), 256 threads.
// Thread layout for accumulate: tx in [0,26) z-cols (4 z each, col 25 = the
// all-ones denominator column), ty in [0,9) gene-rows (7 genes each, stride 9).
__global__ void __launch_bounds__(256) k_attn(const float* __restrict__ gumbel) {
    __shared__ float qs[TG * KDIM];     // 63 x 32
    __shared__ float keys[TC * 36];     // 32 x 32 (pad 36)
    __shared__ float zts[TC * 104];     // 32 x 100 (+ones col, pad 104)
    __shared__ float Esh[TC * 65];      // 32 x 63 (pad 65)

    const int t     = threadIdx.x;
    const int g0    = blockIdx.x * TG;
    const int s     = blockIdx.y;
    const int cbase = s * CELLS_PER_SPLIT;

    // load query tile once
    for (int i = t; i < TG * (KDIM / 4); i += 256) {
        int g = i >> 3;
        int j = (i & 7) << 2;
        int gene = g0 + g;
        float4 v = make_float4(0.f, 0.f, 0.f, 0.f);
        if (gene < N_GENES)
            v = *reinterpret_cast<const float4*>(&d_query[(size_t)gene * KDIM + j]);
        *reinterpret_cast<float4*>(&qs[g * KDIM + j]) = v;
    }

    const int  tx  = t % 26;
    const int  ty  = t / 26;
    const bool act = (t < 234);

    unsigned long long acc2[7][2];
#pragma unroll
    for (int i = 0; i < 7; i++) { acc2[i][0] = 0ULL; acc2[i][1] = 0ULL; }

    for (int tile = 0; tile < NTILES; tile++) {
        const int c0 = cbase + tile * TC;
        __syncthreads();   // previous phase B done before smem reuse

        // load key tile (32x32 floats = 256 float4; one per thread)
        {
            int c = t >> 3;
            int j = (t & 7) << 2;
            *reinterpret_cast<float4*>(&keys[c * 36 + j]) =
                *reinterpret_cast<const float4*>(&d_key[(size_t)(c0 + c) * KDIM + j]);
        }
        // load genZT tile (32x100) + set denominator column
        for (int i = t; i < TC * 25; i += 256) {
            int c = i / 25;
            int j = (i % 25) << 2;
            *reinterpret_cast<float4*>(&zts[c * 104 + j]) =
                *reinterpret_cast<const float4*>(&d_genZT[(size_t)(c0 + c) * ZDIM + j]);
        }
        if (t < TC) {
            zts[t * 104 + 100] = 1.0f;
            zts[t * 104 + 101] = 0.0f;
            zts[t * 104 + 102] = 0.0f;
            zts[t * 104 + 103] = 0.0f;
        }
        __syncthreads();

        // ---- phase A: E[c][g] = exp(q.k/sqrt(32) + gumbel) ----
#pragma unroll
        for (int it = 0; it < 8; it++) {
            int slot = t + it * 256;
            if (slot < TG * TC) {
                int c = slot & (TC - 1);   // lane == c  -> coalesced gumbel
                int g = slot >> 5;
                const ulonglong2* qp = reinterpret_cast<const ulonglong2*>(&qs[g * KDIM]);
                const ulonglong2* kp = reinterpret_cast<const ulonglong2*>(&keys[c * 36]);
                unsigned long long a0 = 0ULL, a1 = 0ULL;
#pragma unroll
                for (int j = 0; j < 8; j++) {
                    ulonglong2 qv = qp[j];
                    ulonglong2 kv = kp[j];
                    fma2(a0, qv.x, kv.x);
                    fma2(a1, qv.y, kv.y);
                }
                float s0, s1, s2, s3;
                unpack2(a0, s0, s1);
                unpack2(a1, s2, s3);
                float dot = (s0 + s2) + (s1 + s3);
                float e = 0.0f;
                int gene = g0 + g;
                if (gene < N_GENES) {
                    float gm = gumbel[(size_t)gene * N_CELLS + (c0 + c)];
                    e = __expf(fmaf(dot, 0.17677669529663687f, gm));
                }
                Esh[c * 65 + g] = e;
            }
        }
        __syncthreads();

        // ---- phase B: acc[g][z] += e * zT[c][z]  (f32x2 packed) ----
        if (act) {
            const float* zbase = &zts[tx * 4];
#pragma unroll 4
            for (int c = 0; c < TC; c++) {
                ulonglong2 z2 = *reinterpret_cast<const ulonglong2*>(zbase + c * 104);
                const float* Er = &Esh[c * 65 + ty];
#pragma unroll
                for (int i = 0; i < 7; i++) {
                    float e = Er[i * 9];
                    unsigned long long ee = pack2(e, e);
                    fma2(acc2[i][0], ee, z2.x);
                    fma2(acc2[i][1], ee, z2.y);
                }
            }
        }
    }

    // ---- write partials ----
    if (act) {
#pragma unroll
        for (int i = 0; i < 7; i++) {
            int gene = g0 + ty + 9 * i;
            if (gene < N_GENES) {
                float o0, o1, o2, o3;
                unpack2(acc2[i][0], o0, o1);
                unpack2(acc2[i][1], o2, o3);
                if (tx < 25) {
                    float4 v = make_float4(o0, o1, o2, o3);
                    *reinterpret_cast<float4*>(
                        &d_pnum[((size_t)s * N_GENES + gene) * ZDIM + tx * 4]) = v;
                } else {
                    d_pden[s * N_GENES + gene] = o0;  // ones-column accumulator
                }
            }
        }
    }
}

// ---------------- K4: combine splits + normalize + transpose to (Z, G) ------
__global__ void k_combine(float* __restrict__ out) {
    int t = blockIdx.x * 256 + threadIdx.x;
    if (t >= N_GENES * ZDIM) return;
    int g = t / ZDIM, z = t % ZDIM;
    float num = 0.f, den = 0.f;
#pragma unroll
    for (int s = 0; s < NSPLIT; s++) {
        num += d_pnum[((size_t)s * N_GENES + g) * ZDIM + z];
        den += d_pden[s * N_GENES + g];
    }
    out[(size_t)z * N_GENES + g] = num / den;
}

// ---------------- launch -----------------------------------------------------
extern "C" void kernel_launch(void* const* d_in, const int* in_sizes, int n_in,
                              void* d_out, int out_size) {
    (void)in_sizes; (void)n_in; (void)out_size;
    const float* rawZ   = (const float*)d_in[0];
    const float* genZ   = (const float*)d_in[1];
    const float* Grep   = (const float*)d_in[2];
    const float* gumbel = (const float*)d_in[3];
    const float* Wz1    = (const float*)d_in[4];
    const float* bz1    = (const float*)d_in[5];
    const float* Wz2    = (const float*)d_in[6];
    const float* bz2    = (const float*)d_in[7];
    const float* Wg1    = (const float*)d_in[8];
    const float* bg1    = (const float*)d_in[9];
    const float* Wg2    = (const float*)d_in[10];
    const float* bg2    = (const float*)d_in[11];
    float* out = (float*)d_out;

    k_transpose<<<dim3(N_CELLS / 32, (ZDIM + 31) / 32), dim3(32, 8)>>>(genZ);
    k_key<<<N_CELLS / 32, 256>>>(rawZ, Wz1, bz1, Wz2, bz2);
    k_query<<<(N_GENES + 7) / 8, 256>>>(Grep, Wg1, bg1, Wg2, bg2);
    k_attn<<<dim3(GTILES, NSPLIT), 256>>>(gumbel);
    k_combine<<<(N_GENES * ZDIM + 255) / 256, 256>>>(out);
}

// round 2
// speedup vs baseline: 1.0005x; 1.0005x over previous
#include <cuda_runtime.h>
#include <math.h>

#define N_GENES 10000
#define N_CELLS 8192
#define ZDIM    100
#define KDIM    32
#define HDIM    256

#define TG 63
#define TC 32
#define NSPLIT 4
#define CELLS_PER_SPLIT (N_CELLS / NSPLIT)   // 2048
#define NTILES (CELLS_PER_SPLIT / TC)        // 64
#define GTILES ((N_GENES + TG - 1) / TG)     // 159

// ---------------- scratch (static device memory; no allocations) ------------
__device__ float d_key[N_CELLS * KDIM];                         // (8192, 32)
__device__ float d_query[N_GENES * KDIM];                       // (10000, 32)
__device__ float d_genZT[N_CELLS * ZDIM];                       // (8192, 100)
__device__ float d_pnum[(size_t)NSPLIT * N_GENES * ZDIM];       // 16 MB partials
__device__ float d_pden[NSPLIT * N_GENES];

// ---------------- f32x2 packed-FMA helpers ----------------------------------
__device__ __forceinline__ unsigned long long pack2(float lo, float hi) {
    unsigned long long r;
    asm("mov.b64 %0, {%1, %2};" : "=l"(r) : "f"(lo), "f"(hi));
    return r;
}
__device__ __forceinline__ void unpack2(unsigned long long v, float& lo, float& hi) {
    asm("mov.b64 {%0, %1}, %2;" : "=f"(lo), "=f"(hi) : "l"(v));
}
__device__ __forceinline__ void fma2(unsigned long long& d, unsigned long long a, unsigned long long b) {
    asm("fma.rn.f32x2 %0, %1, %2, %0;" : "+l"(d) : "l"(a), "l"(b));
}
__device__ __forceinline__ float gelu_f(float x) {
    // exact GELU: x * 0.5 * (1 + erf(x / sqrt(2)))   (approximate=False)
    return 0.5f * x * (1.0f + erff(x * 0.70710678118654752440f));
}

// ---------------- K0: transpose gen_Z (100 x 8192) -> genZT (8192 x 100) ----
__global__ void k_transpose(const float* __restrict__ genZ) {
    __shared__ float tile[32][33];
    int c0 = blockIdx.x * 32, z0 = blockIdx.y * 32;
    int tx = threadIdx.x, ty = threadIdx.y;  // (32, 8)
#pragma unroll
    for (int r = 0; r < 32; r += 8) {
        int z = z0 + ty + r;
        tile[ty + r][tx] = (z < ZDIM) ? genZ[(size_t)z * N_CELLS + c0 + tx] : 0.0f;
    }
    __syncthreads();
#pragma unroll
    for (int r = 0; r < 32; r += 8) {
        int c = c0 + ty + r;
        int z = z0 + tx;
        if (z < ZDIM) d_genZT[(size_t)c * ZDIM + z] = tile[tx][ty + r];
    }
}

// ---------------- K1: key MLP: (8192 cells) -> d_key[c][k] ------------------
// block = 256 threads, 32 cells per block, 256 blocks.
__global__ void __launch_bounds__(256) k_key(
    const float* __restrict__ rawZ,
    const float* __restrict__ Wz1, const float* __restrict__ bz1,
    const float* __restrict__ Wz2, const float* __restrict__ bz2)
{
    __shared__ float Zs[ZDIM * 32];    // [z][c]
    __shared__ float hs[HDIM * 33];    // [h][c], stride 33
    const int t  = threadIdx.x;
    const int c0 = blockIdx.x * 32;

    for (int i = t; i < ZDIM * 32; i += 256) {
        int z = i >> 5, c = i & 31;
        Zs[i] = rawZ[(size_t)z * N_CELLS + c0 + c];
    }
    __syncthreads();

    // hidden: this thread owns h = t, all 32 cells
    float acc[32];
    {
        float b = bz1[t];
#pragma unroll
        for (int c = 0; c < 32; c++) acc[c] = b;
    }
    for (int z = 0; z < ZDIM; z++) {
        float w = Wz1[z * HDIM + t];
        const float4* zr = reinterpret_cast<const float4*>(&Zs[z * 32]);
#pragma unroll
        for (int u = 0; u < 8; u++) {
            float4 v = zr[u];
            acc[4*u+0] = fmaf(w, v.x, acc[4*u+0]);
            acc[4*u+1] = fmaf(w, v.y, acc[4*u+1]);
            acc[4*u+2] = fmaf(w, v.z, acc[4*u+2]);
            acc[4*u+3] = fmaf(w, v.w, acc[4*u+3]);
        }
    }
#pragma unroll
    for (int c = 0; c < 32; c++) hs[t * 33 + c] = gelu_f(acc[c]);
    __syncthreads();

    // key: k = t&31, 4 cells per thread
    const int k = t & 31, cg = t >> 5;
    float a0 = bz2[k], a1 = a0, a2 = a0, a3 = a0;
    for (int h = 0; h < HDIM; h++) {
        float w = Wz2[h * KDIM + k];
        const float* hr = &hs[h * 33 + cg * 4];
        a0 = fmaf(w, hr[0], a0);
        a1 = fmaf(w, hr[1], a1);
        a2 = fmaf(w, hr[2], a2);
        a3 = fmaf(w, hr[3], a3);
    }
    int c = c0 + cg * 4;
    d_key[(size_t)(c + 0) * KDIM + k] = a0;
    d_key[(size_t)(c + 1) * KDIM + k] = a1;
    d_key[(size_t)(c + 2) * KDIM + k] = a2;
    d_key[(size_t)(c + 3) * KDIM + k] = a3;
}

// ---------------- K2: query MLP: (10000 genes) -> d_query[g][k] -------------
// one warp per gene
__global__ void k_query(
    const float* __restrict__ Grep,
    const float* __restrict__ Wg1, const float* __restrict__ bg1,
    const float* __restrict__ Wg2, const float* __restrict__ bg2)
{
    int gene = blockIdx.x * 8 + (threadIdx.x >> 5);
    int k    = threadIdx.x & 31;
    if (gene >= N_GENES) return;
    float h = bg1[k];
    const float* grow = &Grep[(size_t)gene * 100];
    for (int j = 0; j < 100; j++)
        h = fmaf(grow[j], Wg1[j * 32 + k], h);
    h = gelu_f(h);
    float q = bg2[k];
#pragma unroll
    for (int j = 0; j < 32; j++) {
        float hj = __shfl_sync(0xffffffffu, h, j);
        q = fmaf(hj, Wg2[j * 32 + k], q);
    }
    d_query[(size_t)gene * KDIM + k] = q;
}

// ---------------- K3: fused scores+gumbel -> exp -> weighted accumulate -----
// grid = (GTILES, NSPLIT), 256 threads.
// Thread layout for accumulate: tx in [0,26) z-cols (4 z each, col 25 = the
// all-ones denominator column), ty in [0,9) gene-rows (7 genes each, stride 9).
__global__ void __launch_bounds__(256) k_attn(const float* __restrict__ gumbel) {
    __shared__ float qs[TG * KDIM];     // 63 x 32
    __shared__ float keys[TC * 36];     // 32 x 32 (pad 36)
    __shared__ float zts[TC * 104];     // 32 x 100 (+ones col, pad 104)
    __shared__ float Esh[TC * 65];      // 32 x 63 (pad 65)

    const int t     = threadIdx.x;
    const int g0    = blockIdx.x * TG;
    const int s     = blockIdx.y;
    const int cbase = s * CELLS_PER_SPLIT;

    // load query tile once
    for (int i = t; i < TG * (KDIM / 4); i += 256) {
        int g = i >> 3;
        int j = (i & 7) << 2;
        int gene = g0 + g;
        float4 v = make_float4(0.f, 0.f, 0.f, 0.f);
        if (gene < N_GENES)
            v = *reinterpret_cast<const float4*>(&d_query[(size_t)gene * KDIM + j]);
        *reinterpret_cast<float4*>(&qs[g * KDIM + j]) = v;
    }

    const int  tx  = t % 26;
    const int  ty  = t / 26;
    const bool act = (t < 234);

    unsigned long long acc2[7][2];
#pragma unroll
    for (int i = 0; i < 7; i++) { acc2[i][0] = 0ULL; acc2[i][1] = 0ULL; }

    for (int tile = 0; tile < NTILES; tile++) {
        const int c0 = cbase + tile * TC;
        __syncthreads();   // previous phase B done before smem reuse

        // load key tile (32x32 floats = 256 float4; one per thread)
        {
            int c = t >> 3;
            int j = (t & 7) << 2;
            *reinterpret_cast<float4*>(&keys[c * 36 + j]) =
                *reinterpret_cast<const float4*>(&d_key[(size_t)(c0 + c) * KDIM + j]);
        }
        // load genZT tile (32x100) + set denominator column
        for (int i = t; i < TC * 25; i += 256) {
            int c = i / 25;
            int j = (i % 25) << 2;
            *reinterpret_cast<float4*>(&zts[c * 104 + j]) =
                *reinterpret_cast<const float4*>(&d_genZT[(size_t)(c0 + c) * ZDIM + j]);
        }
        if (t < TC) {
            zts[t * 104 + 100] = 1.0f;
            zts[t * 104 + 101] = 0.0f;
            zts[t * 104 + 102] = 0.0f;
            zts[t * 104 + 103] = 0.0f;
        }
        __syncthreads();

        // ---- phase A: E[c][g] = exp(q.k/sqrt(32) + gumbel) ----
#pragma unroll
        for (int it = 0; it < 8; it++) {
            int slot = t + it * 256;
            if (slot < TG * TC) {
                int c = slot & (TC - 1);   // lane == c  -> coalesced gumbel
                int g = slot >> 5;
                const ulonglong2* qp = reinterpret_cast<const ulonglong2*>(&qs[g * KDIM]);
                const ulonglong2* kp = reinterpret_cast<const ulonglong2*>(&keys[c * 36]);
                unsigned long long a0 = 0ULL, a1 = 0ULL;
#pragma unroll
                for (int j = 0; j < 8; j++) {
                    ulonglong2 qv = qp[j];
                    ulonglong2 kv = kp[j];
                    fma2(a0, qv.x, kv.x);
                    fma2(a1, qv.y, kv.y);
                }
                float s0, s1, s2, s3;
                unpack2(a0, s0, s1);
                unpack2(a1, s2, s3);
                float dot = (s0 + s2) + (s1 + s3);
                float e = 0.0f;
                int gene = g0 + g;
                if (gene < N_GENES) {
                    float gm = gumbel[(size_t)gene * N_CELLS + (c0 + c)];
                    e = __expf(fmaf(dot, 0.17677669529663687f, gm));
                }
                Esh[c * 65 + g] = e;
            }
        }
        __syncthreads();

        // ---- phase B: acc[g][z] += e * zT[c][z]  (f32x2 packed) ----
        if (act) {
            const float* zbase = &zts[tx * 4];
#pragma unroll 4
            for (int c = 0; c < TC; c++) {
                ulonglong2 z2 = *reinterpret_cast<const ulonglong2*>(zbase + c * 104);
                const float* Er = &Esh[c * 65 + ty];
#pragma unroll
                for (int i = 0; i < 7; i++) {
                    float e = Er[i * 9];
                    unsigned long long ee = pack2(e, e);
                    fma2(acc2[i][0], ee, z2.x);
                    fma2(acc2[i][1], ee, z2.y);
                }
            }
        }
    }

    // ---- write partials ----
    if (act) {
#pragma unroll
        for (int i = 0; i < 7; i++) {
            int gene = g0 + ty + 9 * i;
            if (gene < N_GENES) {
                float o0, o1, o2, o3;
                unpack2(acc2[i][0], o0, o1);
                unpack2(acc2[i][1], o2, o3);
                if (tx < 25) {
                    float4 v = make_float4(o0, o1, o2, o3);
                    *reinterpret_cast<float4*>(
                        &d_pnum[((size_t)s * N_GENES + gene) * ZDIM + tx * 4]) = v;
                } else {
                    d_pden[s * N_GENES + gene] = o0;  // ones-column accumulator
                }
            }
        }
    }
}

// ---------------- K4: combine splits + normalize + transpose to (Z, G) ------
__global__ void k_combine(float* __restrict__ out) {
    int t = blockIdx.x * 256 + threadIdx.x;
    if (t >= N_GENES * ZDIM) return;
    int g = t / ZDIM, z = t % ZDIM;
    float num = 0.f, den = 0.f;
#pragma unroll
    for (int s = 0; s < NSPLIT; s++) {
        num += d_pnum[((size_t)s * N_GENES + g) * ZDIM + z];
        den += d_pden[s * N_GENES + g];
    }
    out[(size_t)z * N_GENES + g] = num / den;
}

// ---------------- launch -----------------------------------------------------
extern "C" void kernel_launch(void* const* d_in, const int* in_sizes, int n_in,
                              void* d_out, int out_size) {
    (void)in_sizes; (void)n_in; (void)out_size;
    const float* rawZ   = (const float*)d_in[0];
    const float* genZ   = (const float*)d_in[1];
    const float* Grep   = (const float*)d_in[2];
    const float* gumbel = (const float*)d_in[3];
    const float* Wz1    = (const float*)d_in[4];
    const float* bz1    = (const float*)d_in[5];
    const float* Wz2    = (const float*)d_in[6];
    const float* bz2    = (const float*)d_in[7];
    const float* Wg1    = (const float*)d_in[8];
    const float* bg1    = (const float*)d_in[9];
    const float* Wg2    = (const float*)d_in[10];
    const float* bg2    = (const float*)d_in[11];
    float* out = (float*)d_out;

    k_transpose<<<dim3(N_CELLS / 32, (ZDIM + 31) / 32), dim3(32, 8)>>>(genZ);
    k_key<<<N_CELLS / 32, 256>>>(rawZ, Wz1, bz1, Wz2, bz2);
    k_query<<<(N_GENES + 7) / 8, 256>>>(Grep, Wg1, bg1, Wg2, bg2);
    k_attn<<<dim3(GTILES, NSPLIT), 256>>>(gumbel);
    k_combine<<<(N_GENES * ZDIM + 255) / 256, 256>>>(out);
}

// round 4
// speedup vs baseline: 1.9947x; 1.9936x over previous
#include <cuda_runtime.h>
#include <cstdint>
#include <math.h>

#define N_GENES 10000
#define N_CELLS 8192
#define ZDIM    100
#define KDIM    32
#define HDIM    256

#define NSPLIT  4
#define CPB     (N_CELLS / NSPLIT)           // 2048
#define TC      32
#define NTILES  (CPB / TC)                   // 64
#define GT      128
#define GTILES  ((N_GENES + GT - 1) / GT)    // 79

// ---------------- static device scratch ------------------------------------
__device__ float d_key[N_CELLS * KDIM];
__device__ float d_query[N_GENES * KDIM];
__device__ float d_pnum[(size_t)NSPLIT * N_GENES * ZDIM];
__device__ float d_pden[NSPLIT * N_GENES];

// ---------------- smem layout (float2 / float granularity) ------------------
// QP: [128][36] float2 (hi,lo)        36864 B   @ 0
// KP: [32][36]  float2 (hi,lo)         9216 B   @ 36864
// ZP: [104][20] float2 (cell k, k+4)  16640 B   @ 46080
// EE: [128][36] float                 18432 B   @ 62720
#define SMEM_BYTES 81152
#define QP_OFF 0
#define KP_OFF 36864
#define ZP_OFF 46080
#define EE_OFF 62720

__device__ __forceinline__ float tf32r(float x) {
    uint32_t u;
    asm("cvt.rna.tf32.f32 %0, %1;" : "=r"(u) : "f"(x));
    return __uint_as_float(u);
}
__device__ __forceinline__ void mma_tf32(float c[4],
                                         uint32_t a0, uint32_t a1, uint32_t a2, uint32_t a3,
                                         uint32_t b0, uint32_t b1) {
    asm volatile(
        "mma.sync.aligned.m16n8k8.row.col.f32.tf32.tf32.f32 "
        "{%0,%1,%2,%3}, {%4,%5,%6,%7}, {%8,%9}, {%0,%1,%2,%3};"
        : "+f"(c[0]), "+f"(c[1]), "+f"(c[2]), "+f"(c[3])
        : "r"(a0), "r"(a1), "r"(a2), "r"(a3), "r"(b0), "r"(b1));
}
__device__ __forceinline__ float gelu_f(float x) {
    return 0.5f * x * (1.0f + erff(x * 0.70710678118654752440f));
}

// ---------------- K1: key MLP -> d_key[c][k] --------------------------------
__global__ void __launch_bounds__(256) k_key(
    const float* __restrict__ rawZ,
    const float* __restrict__ Wz1, const float* __restrict__ bz1,
    const float* __restrict__ Wz2, const float* __restrict__ bz2)
{
    __shared__ float Zs[ZDIM * 32];
    __shared__ float hs[HDIM * 33];
    const int t = threadIdx.x;
    const int c0 = blockIdx.x * 32;
    for (int i = t; i < ZDIM * 32; i += 256) {
        int z = i >> 5, c = i & 31;
        Zs[i] = rawZ[(size_t)z * N_CELLS + c0 + c];
    }
    __syncthreads();
    float acc[32];
    {
        float b = bz1[t];
#pragma unroll
        for (int c = 0; c < 32; c++) acc[c] = b;
    }
    for (int z = 0; z < ZDIM; z++) {
        float w = Wz1[z * HDIM + t];
        const float4* zr = reinterpret_cast<const float4*>(&Zs[z * 32]);
#pragma unroll
        for (int u = 0; u < 8; u++) {
            float4 v = zr[u];
            acc[4*u+0] = fmaf(w, v.x, acc[4*u+0]);
            acc[4*u+1] = fmaf(w, v.y, acc[4*u+1]);
            acc[4*u+2] = fmaf(w, v.z, acc[4*u+2]);
            acc[4*u+3] = fmaf(w, v.w, acc[4*u+3]);
        }
    }
#pragma unroll
    for (int c = 0; c < 32; c++) hs[t * 33 + c] = gelu_f(acc[c]);
    __syncthreads();
    const int k = t & 31, cg = t >> 5;
    float a0 = bz2[k], a1 = a0, a2 = a0, a3 = a0;
    for (int h = 0; h < HDIM; h++) {
        float w = Wz2[h * KDIM + k];
        const float* hr = &hs[h * 33 + cg * 4];
        a0 = fmaf(w, hr[0], a0);
        a1 = fmaf(w, hr[1], a1);
        a2 = fmaf(w, hr[2], a2);
        a3 = fmaf(w, hr[3], a3);
    }
    int c = c0 + cg * 4;
    d_key[(size_t)(c + 0) * KDIM + k] = a0;
    d_key[(size_t)(c + 1) * KDIM + k] = a1;
    d_key[(size_t)(c + 2) * KDIM + k] = a2;
    d_key[(size_t)(c + 3) * KDIM + k] = a3;
}

// ---------------- K2: query MLP -> d_query[g][k] ----------------------------
__global__ void k_query(
    const float* __restrict__ Grep,
    const float* __restrict__ Wg1, const float* __restrict__ bg1,
    const float* __restrict__ Wg2, const float* __restrict__ bg2)
{
    int gene = blockIdx.x * 8 + (threadIdx.x >> 5);
    int k = threadIdx.x & 31;
    if (gene >= N_GENES) return;
    float h = bg1[k];
    const float* grow = &Grep[(size_t)gene * 100];
    for (int j = 0; j < 100; j++)
        h = fmaf(grow[j], Wg1[j * 32 + k], h);
    h = gelu_f(h);
    float q = bg2[k];
#pragma unroll
    for (int j = 0; j < 32; j++) {
        float hj = __shfl_sync(0xffffffffu, h, j);
        q = fmaf(hj, Wg2[j * 32 + k], q);
    }
    d_query[(size_t)gene * KDIM + k] = q;
}

// ---------------- K3: fused mma.sync tf32 flash attention -------------------
__global__ void __launch_bounds__(256, 2) k_attn(const float* __restrict__ gumbel,
                                                 const float* __restrict__ genZ) {
    extern __shared__ __align__(16) char smem[];
    float2* QP = reinterpret_cast<float2*>(smem + QP_OFF);
    float2* KP = reinterpret_cast<float2*>(smem + KP_OFF);
    float2* ZP = reinterpret_cast<float2*>(smem + ZP_OFF);
    float*  ZPf = reinterpret_cast<float*>(smem + ZP_OFF);
    float*  EE = reinterpret_cast<float*>(smem + EE_OFF);

    const int t = threadIdx.x;
    const int w = t >> 5, lane = t & 31;
    const int quad = lane >> 2, qi = lane & 3;
    const int g0 = blockIdx.x * GT;
    const int s = blockIdx.y;
    const int cbase = s * CPB;
    const int wg0 = w * 16;                 // warp's gene-row base in tile
    const int gene0 = g0 + wg0 + quad;      // first gene (row r)
    const int gene1 = gene0 + 8;            // second gene (row r+8)
    const bool ok0 = gene0 < N_GENES, ok1 = gene1 < N_GENES;
    const float SC = 0.17677669529663687f;  // 1/sqrt(32)

    // ---- prologue: Q hi/lo into QP; constant Z rows 100..103 ----
    for (int idx = t; idx < 128 * 8; idx += 256) {
        int row = idx >> 3, k4 = (idx & 7) * 4;
        int gene = g0 + row;
        float4 v = make_float4(0.f, 0.f, 0.f, 0.f);
        if (gene < N_GENES)
            v = *reinterpret_cast<const float4*>(&d_query[(size_t)gene * KDIM + k4]);
        float h;
        h = tf32r(v.x); QP[row * 36 + k4 + 0] = make_float2(h, v.x - h);
        h = tf32r(v.y); QP[row * 36 + k4 + 1] = make_float2(h, v.y - h);
        h = tf32r(v.z); QP[row * 36 + k4 + 2] = make_float2(h, v.z - h);
        h = tf32r(v.w); QP[row * 36 + k4 + 3] = make_float2(h, v.w - h);
    }
    if (t < 128) {
        int z = 100 + (t >> 5), p = t & 31;
        ZPf[z * 40 + p] = (z == 100) ? 1.0f : 0.0f;
    }

    float O[13][4];
#pragma unroll
    for (int nt = 0; nt < 13; nt++)
#pragma unroll
        for (int e = 0; e < 4; e++) O[nt][e] = 0.0f;

    for (int it = 0; it < NTILES; it++) {
        const int c0 = cbase + it * TC;

        // gumbel prefetch (C-fragment layout), streaming
        float2 gv[2][4];
#pragma unroll
        for (int nt = 0; nt < 4; nt++) {
            gv[0][nt] = ok0 ? __ldcs(reinterpret_cast<const float2*>(
                            &gumbel[(size_t)gene0 * N_CELLS + c0 + nt * 8 + 2 * qi]))
                            : make_float2(0.f, 0.f);
            gv[1][nt] = ok1 ? __ldcs(reinterpret_cast<const float2*>(
                            &gumbel[(size_t)gene1 * N_CELLS + c0 + nt * 8 + 2 * qi]))
                            : make_float2(0.f, 0.f);
        }

        __syncthreads();   // all warps done reading KP/ZP of previous tile

        // cooperative load: K tile (hi/lo packed)
        {
            int c = t >> 3, k4 = (t & 7) * 4;
            float4 v = *reinterpret_cast<const float4*>(&d_key[(size_t)(c0 + c) * KDIM + k4]);
            float h;
            h = tf32r(v.x); KP[c * 36 + k4 + 0] = make_float2(h, v.x - h);
            h = tf32r(v.y); KP[c * 36 + k4 + 1] = make_float2(h, v.y - h);
            h = tf32r(v.z); KP[c * 36 + k4 + 2] = make_float2(h, v.z - h);
            h = tf32r(v.w); KP[c * 36 + k4 + 3] = make_float2(h, v.w - h);
        }
        // cooperative load: Z tile (tf32, (k,k+4)-paired layout)
        for (int idx = t; idx < 100 * 8; idx += 256) {
            int z = idx >> 3, cq = idx & 7;
            float4 v = *reinterpret_cast<const float4*>(&genZ[(size_t)z * N_CELLS + c0 + cq * 4]);
            float vv[4] = {tf32r(v.x), tf32r(v.y), tf32r(v.z), tf32r(v.w)};
#pragma unroll
            for (int j = 0; j < 4; j++) {
                int cell = cq * 4 + j;
                int ks = cell >> 3, klo = cell & 7;
                int pos = (ks * 4 + (klo & 3)) * 2 + (klo >> 2);
                ZPf[z * 40 + pos] = vv[j];
            }
        }
        __syncthreads();

        // ---- phase A: scores via 3-product tf32 mma ----
        float C1[4][4];
#pragma unroll
        for (int nt = 0; nt < 4; nt++)
#pragma unroll
            for (int e = 0; e < 4; e++) C1[nt][e] = 0.0f;

#pragma unroll
        for (int ks = 0; ks < 4; ks++) {
            float2 A0 = QP[(wg0 + quad) * 36 + ks * 8 + qi];
            float2 A1 = QP[(wg0 + quad + 8) * 36 + ks * 8 + qi];
            float2 A2 = QP[(wg0 + quad) * 36 + ks * 8 + qi + 4];
            float2 A3 = QP[(wg0 + quad + 8) * 36 + ks * 8 + qi + 4];
            uint32_t a0h = __float_as_uint(A0.x), a0l = __float_as_uint(A0.y);
            uint32_t a1h = __float_as_uint(A1.x), a1l = __float_as_uint(A1.y);
            uint32_t a2h = __float_as_uint(A2.x), a2l = __float_as_uint(A2.y);
            uint32_t a3h = __float_as_uint(A3.x), a3l = __float_as_uint(A3.y);
#pragma unroll
            for (int nt = 0; nt < 4; nt++) {
                float2 B0 = KP[(nt * 8 + quad) * 36 + ks * 8 + qi];
                float2 B1 = KP[(nt * 8 + quad) * 36 + ks * 8 + qi + 4];
                uint32_t b0h = __float_as_uint(B0.x), b0l = __float_as_uint(B0.y);
                uint32_t b1h = __float_as_uint(B1.x), b1l = __float_as_uint(B1.y);
                mma_tf32(C1[nt], a0h, a1h, a2h, a3h, b0h, b1h);
                mma_tf32(C1[nt], a0h, a1h, a2h, a3h, b0l, b1l);
                mma_tf32(C1[nt], a0l, a1l, a2l, a3l, b0h, b1h);
            }
        }

        // ---- exp + gumbel -> E (tf32) into smem ----
#pragma unroll
        for (int nt = 0; nt < 4; nt++) {
            float e0 = tf32r(__expf(fmaf(C1[nt][0], SC, gv[0][nt].x)));
            float e1 = tf32r(__expf(fmaf(C1[nt][1], SC, gv[0][nt].y)));
            float e2 = tf32r(__expf(fmaf(C1[nt][2], SC, gv[1][nt].x)));
            float e3 = tf32r(__expf(fmaf(C1[nt][3], SC, gv[1][nt].y)));
            *reinterpret_cast<float2*>(&EE[(wg0 + quad) * 36 + nt * 8 + 2 * qi]) =
                make_float2(e0, e1);
            *reinterpret_cast<float2*>(&EE[(wg0 + quad + 8) * 36 + nt * 8 + 2 * qi]) =
                make_float2(e2, e3);
        }
        __syncwarp();   // E exchange is intra-warp (same quad rows)

        // ---- phase B: O += E * Zt ----
#pragma unroll
        for (int ks = 0; ks < 4; ks++) {
            uint32_t a0 = __float_as_uint(EE[(wg0 + quad) * 36 + ks * 8 + qi]);
            uint32_t a1 = __float_as_uint(EE[(wg0 + quad + 8) * 36 + ks * 8 + qi]);
            uint32_t a2 = __float_as_uint(EE[(wg0 + quad) * 36 + ks * 8 + qi + 4]);
            uint32_t a3 = __float_as_uint(EE[(wg0 + quad + 8) * 36 + ks * 8 + qi + 4]);
#pragma unroll
            for (int nt = 0; nt < 13; nt++) {
                float2 B = ZP[(nt * 8 + quad) * 20 + ks * 4 + qi];
                mma_tf32(O[nt], a0, a1, a2, a3,
                         __float_as_uint(B.x), __float_as_uint(B.y));
            }
        }
    }

    // ---- epilogue: write partials ----
#pragma unroll
    for (int half = 0; half < 2; half++) {
        int g = g0 + wg0 + quad + half * 8;
        if (g >= N_GENES) continue;
        float* base = &d_pnum[((size_t)s * N_GENES + g) * ZDIM];
#pragma unroll
        for (int nt = 0; nt < 12; nt++)
            *reinterpret_cast<float2*>(&base[nt * 8 + 2 * qi]) =
                make_float2(O[nt][half * 2 + 0], O[nt][half * 2 + 1]);
        int col = 96 + 2 * qi;
        if (col < 100)
            *reinterpret_cast<float2*>(&base[col]) =
                make_float2(O[12][half * 2 + 0], O[12][half * 2 + 1]);
        else if (col == 100)
            d_pden[s * N_GENES + g] = O[12][half * 2 + 0];
    }
}

// ---------------- K4: combine + normalize + transpose -----------------------
__global__ void k_combine(float* __restrict__ out) {
    int t = blockIdx.x * 256 + threadIdx.x;
    if (t >= N_GENES * ZDIM) return;
    int g = t / ZDIM, z = t % ZDIM;
    float num = 0.f, den = 0.f;
#pragma unroll
    for (int sp = 0; sp < NSPLIT; sp++) {
        num += d_pnum[((size_t)sp * N_GENES + g) * ZDIM + z];
        den += d_pden[sp * N_GENES + g];
    }
    out[(size_t)z * N_GENES + g] = num / den;
}

// ---------------- launch ------------------------------------------------------
extern "C" void kernel_launch(void* const* d_in, const int* in_sizes, int n_in,
                              void* d_out, int out_size) {
    (void)in_sizes; (void)n_in; (void)out_size;
    const float* rawZ   = (const float*)d_in[0];
    const float* genZ   = (const float*)d_in[1];
    const float* Grep   = (const float*)d_in[2];
    const float* gumbel = (const float*)d_in[3];
    const float* Wz1    = (const float*)d_in[4];
    const float* bz1    = (const float*)d_in[5];
    const float* Wz2    = (const float*)d_in[6];
    const float* bz2    = (const float*)d_in[7];
    const float* Wg1    = (const float*)d_in[8];
    const float* bg1    = (const float*)d_in[9];
    const float* Wg2    = (const float*)d_in[10];
    const float* bg2    = (const float*)d_in[11];
    float* out = (float*)d_out;

    static bool configured = false;
    if (!configured) {
        cudaFuncSetAttribute(k_attn, cudaFuncAttributeMaxDynamicSharedMemorySize, SMEM_BYTES);
        configured = true;
    }

    k_key<<<N_CELLS / 32, 256>>>(rawZ, Wz1, bz1, Wz2, bz2);
    k_query<<<(N_GENES + 7) / 8, 256>>>(Grep, Wg1, bg1, Wg2, bg2);
    k_attn<<<dim3(GTILES, NSPLIT), 256, SMEM_BYTES>>>(gumbel, genZ);
    k_combine<<<(N_GENES * ZDIM + 255) / 256, 256>>>(out);
}

// round 5
// speedup vs baseline: 3.2799x; 1.6443x over previous
#include <cuda_runtime.h>
#include <cuda_bf16.h>
#include <cstdint>
#include <math.h>

#define N_GENES 10000
#define N_CELLS 8192
#define ZDIM    100
#define KDIM    32
#define HDIM    256

#define NSPLIT  4
#define CPB     (N_CELLS / NSPLIT)           // 2048
#define TC      32
#define NTILES  (CPB / TC)                   // 64
#define GT      128
#define GTILES  ((N_GENES + GT - 1) / GT)    // 79

// ---------------- static device scratch ------------------------------------
__device__ float    d_key[N_CELLS * KDIM];                 // fp32 key MLP out
__device__ uint32_t d_kp[N_CELLS * 32];                    // packed bf16x2 hi|lo, permuted
__device__ float    d_query[N_GENES * KDIM];
__device__ float    d_zp[(size_t)ZDIM * N_CELLS];          // tf32-rounded, cell-permuted
__device__ float    d_pnum[(size_t)NSPLIT * N_GENES * ZDIM];
__device__ float    d_pden[NSPLIT * N_GENES];

// ---------------- smem layout (bytes) ---------------------------------------
// K tiles: 32 rows x 160B (32 uint32 data + pad)     -> 5120 each
// Z tiles: 104 rows x 160B (32 floats data + pad)    -> 16640 each
// E:       128 rows x 160B                           -> 20480
#define SM_K(b)  ((b) * 5120)
#define SM_Z(b)  (10240 + (b) * 16640)
#define SM_E     43520
#define SMEM_BYTES 64000

__device__ __forceinline__ uint32_t smem_u32(const void* p) {
    uint32_t a;
    asm("{ .reg .u64 t; cvta.to.shared.u64 t, %1; cvt.u32.u64 %0, t; }" : "=r"(a) : "l"(p));
    return a;
}
__device__ __forceinline__ float tf32r(float x) {
    uint32_t u;
    asm("cvt.rna.tf32.f32 %0, %1;" : "=r"(u) : "f"(x));
    return __uint_as_float(u);
}
#define CP_ASYNC16(dst, src) \
    asm volatile("cp.async.cg.shared.global [%0], [%1], 16;" :: "r"(dst), "l"(src))
#define CP_COMMIT() asm volatile("cp.async.commit_group;")
#define CP_WAIT0()  asm volatile("cp.async.wait_group 0;" ::: "memory")

__device__ __forceinline__ void mma_bf16(float c[4],
                                         uint32_t a0, uint32_t a1, uint32_t a2, uint32_t a3,
                                         uint32_t b0, uint32_t b1) {
    asm volatile(
        "mma.sync.aligned.m16n8k16.row.col.f32.bf16.bf16.f32 "
        "{%0,%1,%2,%3}, {%4,%5,%6,%7}, {%8,%9}, {%0,%1,%2,%3};"
        : "+f"(c[0]), "+f"(c[1]), "+f"(c[2]), "+f"(c[3])
        : "r"(a0), "r"(a1), "r"(a2), "r"(a3), "r"(b0), "r"(b1));
}
__device__ __forceinline__ void mma_tf32(float c[4],
                                         uint32_t a0, uint32_t a1, uint32_t a2, uint32_t a3,
                                         uint32_t b0, uint32_t b1) {
    asm volatile(
        "mma.sync.aligned.m16n8k8.row.col.f32.tf32.tf32.f32 "
        "{%0,%1,%2,%3}, {%4,%5,%6,%7}, {%8,%9}, {%0,%1,%2,%3};"
        : "+f"(c[0]), "+f"(c[1]), "+f"(c[2]), "+f"(c[3])
        : "r"(a0), "r"(a1), "r"(a2), "r"(a3), "r"(b0), "r"(b1));
}
__device__ __forceinline__ float2 lds64(uint32_t addr) {
    float2 v;
    asm volatile("ld.shared.v2.f32 {%0,%1}, [%2];" : "=f"(v.x), "=f"(v.y) : "r"(addr));
    return v;
}
__device__ __forceinline__ float gelu_f(float x) {
    return 0.5f * x * (1.0f + erff(x * 0.70710678118654752440f));
}
__device__ __forceinline__ uint32_t pack_bf16(float a, float b) {
    __nv_bfloat162 h = __floats2bfloat162_rn(a, b);
    return *reinterpret_cast<uint32_t*>(&h);
}

// ---------------- K1: key MLP -> d_key[c][k] (fp32) --------------------------
__global__ void __launch_bounds__(256) k_key(
    const float* __restrict__ rawZ,
    const float* __restrict__ Wz1, const float* __restrict__ bz1,
    const float* __restrict__ Wz2, const float* __restrict__ bz2)
{
    __shared__ float Zs[ZDIM * 32];
    __shared__ float hs[HDIM * 33];
    const int t = threadIdx.x;
    const int c0 = blockIdx.x * 32;
    for (int i = t; i < ZDIM * 32; i += 256) {
        int z = i >> 5, c = i & 31;
        Zs[i] = rawZ[(size_t)z * N_CELLS + c0 + c];
    }
    __syncthreads();
    float acc[32];
    {
        float b = bz1[t];
#pragma unroll
        for (int c = 0; c < 32; c++) acc[c] = b;
    }
    for (int z = 0; z < ZDIM; z++) {
        float w = Wz1[z * HDIM + t];
        const float4* zr = reinterpret_cast<const float4*>(&Zs[z * 32]);
#pragma unroll
        for (int u = 0; u < 8; u++) {
            float4 v = zr[u];
            acc[4*u+0] = fmaf(w, v.x, acc[4*u+0]);
            acc[4*u+1] = fmaf(w, v.y, acc[4*u+1]);
            acc[4*u+2] = fmaf(w, v.z, acc[4*u+2]);
            acc[4*u+3] = fmaf(w, v.w, acc[4*u+3]);
        }
    }
#pragma unroll
    for (int c = 0; c < 32; c++) hs[t * 33 + c] = gelu_f(acc[c]);
    __syncthreads();
    const int k = t & 31, cg = t >> 5;
    float a0 = bz2[k], a1 = a0, a2 = a0, a3 = a0;
    for (int h = 0; h < HDIM; h++) {
        float w = Wz2[h * KDIM + k];
        const float* hr = &hs[h * 33 + cg * 4];
        a0 = fmaf(w, hr[0], a0);
        a1 = fmaf(w, hr[1], a1);
        a2 = fmaf(w, hr[2], a2);
        a3 = fmaf(w, hr[3], a3);
    }
    int c = c0 + cg * 4;
    d_key[(size_t)(c + 0) * KDIM + k] = a0;
    d_key[(size_t)(c + 1) * KDIM + k] = a1;
    d_key[(size_t)(c + 2) * KDIM + k] = a2;
    d_key[(size_t)(c + 3) * KDIM + k] = a3;
}

// ---------------- K1b: pack key -> bf16 hi/lo pairs, permuted ----------------
// d_kp[c][slot]      = hi pairs (k=2p,2p+1), slot = ks*8 + (j&3)*2 + (j>>2)
// d_kp[c][16+slot]   = lo pairs
__global__ void k_packK() {
    int tid = blockIdx.x * 256 + threadIdx.x;        // 8192*16 pairs
    if (tid >= N_CELLS * 16) return;
    int c = tid >> 4, p = tid & 15;
    int ks = p >> 3, j = p & 7;
    int slot = ks * 8 + (j & 3) * 2 + (j >> 2);
    float x0 = d_key[c * 32 + 2 * p], x1 = d_key[c * 32 + 2 * p + 1];
    float h0 = __bfloat162float(__float2bfloat16(x0));
    float h1 = __bfloat162float(__float2bfloat16(x1));
    d_kp[c * 32 + slot]      = pack_bf16(h0, h1);
    d_kp[c * 32 + 16 + slot] = pack_bf16(x0 - h0, x1 - h1);
}

// ---------------- K0: genZ -> tf32-rounded, cell-permuted --------------------
__global__ void k_packZ(const float* __restrict__ genZ) {
    int tid = blockIdx.x * 256 + threadIdx.x;        // 100*8192
    if (tid >= ZDIM * N_CELLS) return;
    int z = tid >> 13, c = tid & 8191;
    int j = c & 7;
    int cp = (c & ~7) + (j & 3) * 2 + (j >> 2);
    d_zp[(size_t)z * N_CELLS + cp] = tf32r(genZ[tid]);
}

// ---------------- K2: query MLP -> d_query[g][k] ----------------------------
__global__ void k_query(
    const float* __restrict__ Grep,
    const float* __restrict__ Wg1, const float* __restrict__ bg1,
    const float* __restrict__ Wg2, const float* __restrict__ bg2)
{
    int gene = blockIdx.x * 8 + (threadIdx.x >> 5);
    int k = threadIdx.x & 31;
    if (gene >= N_GENES) return;
    float h = bg1[k];
    const float* grow = &Grep[(size_t)gene * 100];
    for (int j = 0; j < 100; j++)
        h = fmaf(grow[j], Wg1[j * 32 + k], h);
    h = gelu_f(h);
    float q = bg2[k];
#pragma unroll
    for (int j = 0; j < 32; j++) {
        float hj = __shfl_sync(0xffffffffu, h, j);
        q = fmaf(hj, Wg2[j * 32 + k], q);
    }
    d_query[(size_t)gene * KDIM + k] = q;
}

// ---------------- K3: fused flash attention (bf16 scores + tf32 AV) ----------
__global__ void __launch_bounds__(256, 2) k_attn(const float* __restrict__ gumbel) {
    extern __shared__ __align__(16) char smem[];
    const uint32_t sb = smem_u32(smem);
    const int t = threadIdx.x;
    const int w = t >> 5, lane = t & 31;
    const int quad = lane >> 2, qi = lane & 3;
    const int g0 = blockIdx.x * GT;
    const int s = blockIdx.y;
    const int cbase = s * CPB;
    const int wg0 = w * 16;
    const int gene0 = g0 + wg0 + quad;
    const int gene1 = gene0 + 8;
    const bool ok0 = gene0 < N_GENES, ok1 = gene1 < N_GENES;
    const float SC = 0.17677669529663687f;

    // ---- prologue: Q a-frags into registers (bf16 hi/lo) ----
    uint32_t aQh[2][4], aQl[2][4];
#pragma unroll
    for (int ks = 0; ks < 2; ks++) {
#pragma unroll
        for (int r = 0; r < 4; r++) {
            int gg = (r & 1) ? gene1 : gene0;
            int kk = ks * 16 + 2 * qi + ((r & 2) ? 8 : 0);
            float x0 = 0.f, x1 = 0.f;
            if ((r & 1) ? ok1 : ok0) {
                float2 v = *reinterpret_cast<const float2*>(&d_query[(size_t)gg * 32 + kk]);
                x0 = v.x; x1 = v.y;
            }
            float h0 = __bfloat162float(__float2bfloat16(x0));
            float h1 = __bfloat162float(__float2bfloat16(x1));
            aQh[ks][r] = pack_bf16(h0, h1);
            aQl[ks][r] = pack_bf16(x0 - h0, x1 - h1);
        }
    }

    // ---- constant Z rows 100..103 in both buffers ----
    if (t < 128) {
        int z = 100 + (t >> 5), c = t & 31;
        float v = (z == 100) ? 1.0f : 0.0f;
        *reinterpret_cast<float*>(smem + SM_Z(0) + z * 160 + c * 4) = v;
        *reinterpret_cast<float*>(smem + SM_Z(1) + z * 160 + c * 4) = v;
    }

    // ---- cp.async tile 0 ----
    {
        int c0 = cbase;
        int row = t >> 3, ch = t & 7;
        CP_ASYNC16(sb + SM_K(0) + row * 160 + ch * 16,
                   (const char*)(d_kp + (size_t)(c0 + row) * 32 + ch * 4));
        for (int idx = t; idx < 800; idx += 256) {
            int zr = idx >> 3, zc = idx & 7;
            CP_ASYNC16(sb + SM_Z(0) + zr * 160 + zc * 16,
                       (const char*)(d_zp + (size_t)zr * N_CELLS + c0 + zc * 4));
        }
    }
    CP_COMMIT();
    CP_WAIT0();
    __syncthreads();

    float O[13][4];
#pragma unroll
    for (int nt = 0; nt < 13; nt++)
#pragma unroll
        for (int e = 0; e < 4; e++) O[nt][e] = 0.0f;

    // E store positions: cells (2qi, 2qi+1) -> permuted slots
    const int pos0 = (qi & 1) * 4 + (qi >> 1);   // slot of cell 2qi
    // slot of cell 2qi+1 = pos0 + 2

    for (int i = 0; i < NTILES; i++) {
        const int b = i & 1, nb = b ^ 1;
        const int c0 = cbase + i * TC;

        // prefetch tile i+1
        if (i + 1 < NTILES) {
            int c1 = c0 + TC;
            int row = t >> 3, ch = t & 7;
            CP_ASYNC16(sb + SM_K(nb) + row * 160 + ch * 16,
                       (const char*)(d_kp + (size_t)(c1 + row) * 32 + ch * 4));
            for (int idx = t; idx < 800; idx += 256) {
                int zr = idx >> 3, zc = idx & 7;
                CP_ASYNC16(sb + SM_Z(nb) + zr * 160 + zc * 16,
                           (const char*)(d_zp + (size_t)zr * N_CELLS + c1 + zc * 4));
            }
        }
        CP_COMMIT();

        // gumbel prefetch (this tile), streaming
        float2 gv0[4], gv1[4];
#pragma unroll
        for (int nt = 0; nt < 4; nt++) {
            gv0[nt] = ok0 ? __ldcs(reinterpret_cast<const float2*>(
                          &gumbel[(size_t)gene0 * N_CELLS + c0 + nt * 8 + 2 * qi]))
                          : make_float2(0.f, 0.f);
            gv1[nt] = ok1 ? __ldcs(reinterpret_cast<const float2*>(
                          &gumbel[(size_t)gene1 * N_CELLS + c0 + nt * 8 + 2 * qi]))
                          : make_float2(0.f, 0.f);
        }

        // ---- MMA1: scores, 3-product bf16, 8 independent accumulator chains
        float C[8][4];
#pragma unroll
        for (int m = 0; m < 8; m++)
#pragma unroll
            for (int e = 0; e < 4; e++) C[m][e] = 0.0f;

        const uint32_t kbase = sb + SM_K(b);
#pragma unroll
        for (int p = 0; p < 3; p++) {
            const uint32_t* A0 = (p == 1) ? aQl[0] : aQh[0];
            const uint32_t* A1 = (p == 1) ? aQl[1] : aQh[1];
            const uint32_t hl = (p == 2) ? 64u : 0u;   // p2 uses K-lo plane
            // p0: Qh*Kh, p1: Ql*Kh? careful: products = hh, hl(K-lo), lh(Q-lo)
            // p==0: Qh,Kh ; p==1: Ql,Kh ; p==2: Qh,Kl
            const uint32_t* B_A0 = (p == 1) ? aQl[0] : aQh[0]; (void)B_A0;
#pragma unroll
            for (int ks = 0; ks < 2; ks++) {
                const uint32_t* aa = (ks == 0) ? A0 : A1;
#pragma unroll
                for (int nt = 0; nt < 4; nt++) {
                    uint32_t addr = kbase + (nt * 8 + quad) * 160 + (ks * 4 + qi) * 8 + hl;
                    float2 bb = lds64(addr);
                    mma_bf16(C[ks * 4 + nt], aa[0], aa[1], aa[2], aa[3],
                             __float_as_uint(bb.x), __float_as_uint(bb.y));
                }
            }
        }

        // ---- exp + gumbel -> E (tf32 RN) into per-warp smem, permuted ----
        const uint32_t ebase = sb + SM_E;
#pragma unroll
        for (int nt = 0; nt < 4; nt++) {
            float d0 = C[nt][0] + C[4 + nt][0];
            float d1 = C[nt][1] + C[4 + nt][1];
            float d2 = C[nt][2] + C[4 + nt][2];
            float d3 = C[nt][3] + C[4 + nt][3];
            float e0 = tf32r(__expf(fmaf(d0, SC, gv0[nt].x)));
            float e1 = tf32r(__expf(fmaf(d1, SC, gv0[nt].y)));
            float e2 = tf32r(__expf(fmaf(d2, SC, gv1[nt].x)));
            float e3 = tf32r(__expf(fmaf(d3, SC, gv1[nt].y)));
            uint32_t r0 = ebase + (wg0 + quad) * 160 + (nt * 8 + pos0) * 4;
            uint32_t r1 = ebase + (wg0 + quad + 8) * 160 + (nt * 8 + pos0) * 4;
            asm volatile("st.shared.f32 [%0], %1;" :: "r"(r0), "f"(e0));
            asm volatile("st.shared.f32 [%0], %1;" :: "r"(r0 + 8), "f"(e1));
            asm volatile("st.shared.f32 [%0], %1;" :: "r"(r1), "f"(e2));
            asm volatile("st.shared.f32 [%0], %1;" :: "r"(r1 + 8), "f"(e3));
        }
        __syncwarp();

        // ---- MMA2: O += E(tf32) * Z(tf32) ----
        const uint32_t zbase = sb + SM_Z(b);
#pragma unroll
        for (int ks = 0; ks < 4; ks++) {
            float2 ae02 = lds64(ebase + (wg0 + quad) * 160 + (ks * 4 + qi) * 8);
            float2 ae13 = lds64(ebase + (wg0 + quad + 8) * 160 + (ks * 4 + qi) * 8);
            uint32_t a0 = __float_as_uint(ae02.x), a2 = __float_as_uint(ae02.y);
            uint32_t a1 = __float_as_uint(ae13.x), a3 = __float_as_uint(ae13.y);
#pragma unroll
            for (int nt = 0; nt < 13; nt++) {
                float2 bz = lds64(zbase + (nt * 8 + quad) * 160 + (ks * 4 + qi) * 8);
                mma_tf32(O[nt], a0, a1, a2, a3,
                         __float_as_uint(bz.x), __float_as_uint(bz.y));
            }
        }

        CP_WAIT0();
        __syncthreads();
    }

    // ---- epilogue ----
#pragma unroll
    for (int half = 0; half < 2; half++) {
        int g = g0 + wg0 + quad + half * 8;
        if (g >= N_GENES) continue;
        float* base = &d_pnum[((size_t)s * N_GENES + g) * ZDIM];
#pragma unroll
        for (int nt = 0; nt < 12; nt++)
            *reinterpret_cast<float2*>(&base[nt * 8 + 2 * qi]) =
                make_float2(O[nt][half * 2 + 0], O[nt][half * 2 + 1]);
        int col = 96 + 2 * qi;
        if (col < 100)
            *reinterpret_cast<float2*>(&base[col]) =
                make_float2(O[12][half * 2 + 0], O[12][half * 2 + 1]);
        else if (col == 100)
            d_pden[s * N_GENES + g] = O[12][half * 2 + 0];
    }
}

// ---------------- K4: combine + normalize + transpose -----------------------
__global__ void k_combine(float* __restrict__ out) {
    int t = blockIdx.x * 256 + threadIdx.x;
    if (t >= N_GENES * ZDIM) return;
    int g = t / ZDIM, z = t % ZDIM;
    float num = 0.f, den = 0.f;
#pragma unroll
    for (int sp = 0; sp < NSPLIT; sp++) {
        num += d_pnum[((size_t)sp * N_GENES + g) * ZDIM + z];
        den += d_pden[sp * N_GENES + g];
    }
    out[(size_t)z * N_GENES + g] = num / den;
}

// ---------------- launch ------------------------------------------------------
extern "C" void kernel_launch(void* const* d_in, const int* in_sizes, int n_in,
                              void* d_out, int out_size) {
    (void)in_sizes; (void)n_in; (void)out_size;
    const float* rawZ   = (const float*)d_in[0];
    const float* genZ   = (const float*)d_in[1];
    const float* Grep   = (const float*)d_in[2];
    const float* gumbel = (const float*)d_in[3];
    const float* Wz1    = (const float*)d_in[4];
    const float* bz1    = (const float*)d_in[5];
    const float* Wz2    = (const float*)d_in[6];
    const float* bz2    = (const float*)d_in[7];
    const float* Wg1    = (const float*)d_in[8];
    const float* bg1    = (const float*)d_in[9];
    const float* Wg2    = (const float*)d_in[10];
    const float* bg2    = (const float*)d_in[11];
    float* out = (float*)d_out;

    static bool configured = false;
    if (!configured) {
        cudaFuncSetAttribute(k_attn, cudaFuncAttributeMaxDynamicSharedMemorySize, SMEM_BYTES);
        configured = true;
    }

    k_key<<<N_CELLS / 32, 256>>>(rawZ, Wz1, bz1, Wz2, bz2);
    k_packK<<<(N_CELLS * 16 + 255) / 256, 256>>>();
    k_packZ<<<(ZDIM * N_CELLS + 255) / 256, 256>>>(genZ);
    k_query<<<(N_GENES + 7) / 8, 256>>>(Grep, Wg1, bg1, Wg2, bg2);
    k_attn<<<dim3(GTILES, NSPLIT), 256, SMEM_BYTES>>>(gumbel);
    k_combine<<<(N_GENES * ZDIM + 255) / 256, 256>>>(out);
}